// round 1
// baseline (speedup 1.0000x reference)
#include <cuda_runtime.h>
#include <cstdint>

#define BB   16
#define NPP  4096
#define CIN  64
#define MM   1024
#define KK   64
#define HID  64
#define OUTD 128
#define NC   (BB*MM)          /* 16384 centers */
#define R2   0.04f            /* f32(0.2*0.2 in double) == 0.04f */

#define OFF_C 2097152         /* NC*OUTD */
#define OFF_B 2146304         /* OFF_C + NC*3 */

__device__ int   g_fps[NC];
__device__ int   g_nbr[NC*KK];
__device__ int   g_cnt[NC];
__device__ float g_F1[(size_t)BB*NPP*HID];

__device__ __forceinline__ float d2f(float ax,float ay,float az,float bx,float by,float bz){
    float dx=__fsub_rn(ax,bx), dy=__fsub_rn(ay,by), dz=__fsub_rn(az,bz);
    return __fadd_rn(__fadd_rn(__fmul_rn(dx,dx),__fmul_rn(dy,dy)),__fmul_rn(dz,dz));
}

// ---------------------------------------------------------------------------
// Kernel 1: farthest point sampling, one block per cloud.
// ---------------------------------------------------------------------------
__global__ void __launch_bounds__(1024,1) fps_kernel(const float* __restrict__ point){
    extern __shared__ float sm[];
    float* px = sm;
    float* py = sm +   NPP;
    float* pz = sm + 2*NPP;
    float* dd = sm + 3*NPP;
    __shared__ float wv[32];
    __shared__ int   wi[32];
    __shared__ int   selSh;

    int b = blockIdx.x, tid = threadIdx.x, lane = tid & 31, warp = tid >> 5;
    const float* P = point + (size_t)b*NPP*3;
    for (int i = tid; i < NPP; i += 1024){
        px[i] = P[i*3+0]; py[i] = P[i*3+1]; pz[i] = P[i*3+2];
        dd[i] = 3.402823466e38f;
    }
    if (tid == 0) g_fps[b*MM] = 0;
    __syncthreads();

    int last = 0;
    for (int m = 1; m < MM; m++){
        float cx = px[last], cy = py[last], cz = pz[last];
        float bv = -1.f; int bi = NPP;
        #pragma unroll
        for (int r = 0; r < 4; r++){
            int i = tid + r*1024;
            float nd = d2f(px[i], py[i], pz[i], cx, cy, cz);
            float v  = fminf(dd[i], nd);
            dd[i] = v;
            if (v > bv || (v == bv && i < bi)){ bv = v; bi = i; }
        }
        #pragma unroll
        for (int s = 16; s; s >>= 1){
            float ov = __shfl_xor_sync(0xffffffffu, bv, s);
            int   oi = __shfl_xor_sync(0xffffffffu, bi, s);
            if (ov > bv || (ov == bv && oi < bi)){ bv = ov; bi = oi; }
        }
        if (lane == 0){ wv[warp] = bv; wi[warp] = bi; }
        __syncthreads();
        if (warp == 0){
            bv = wv[lane]; bi = wi[lane];
            #pragma unroll
            for (int s = 16; s; s >>= 1){
                float ov = __shfl_xor_sync(0xffffffffu, bv, s);
                int   oi = __shfl_xor_sync(0xffffffffu, bi, s);
                if (ov > bv || (ov == bv && oi < bi)){ bv = ov; bi = oi; }
            }
            if (lane == 0) selSh = bi;
        }
        __syncthreads();
        last = selSh;
        if (tid == 0) g_fps[b*MM + m] = last;
    }
}

// ---------------------------------------------------------------------------
// Kernel 2: F1 = feat @ W1[:64] + b1   (layer-1 feature part, per point)
// ---------------------------------------------------------------------------
__global__ void __launch_bounds__(256) f1_kernel(const float* __restrict__ xyz,
                                                 const float* __restrict__ W1,
                                                 const float* __restrict__ b1){
    __shared__ float Ws[CIN*HID];
    __shared__ float bs[HID];
    int tid = threadIdx.x;
    for (int i = tid; i < CIN*HID; i += 256) Ws[i] = W1[i];
    if (tid < HID) bs[tid] = b1[tid];
    __syncthreads();

    int row = blockIdx.x*256 + tid;
    float f[CIN];
    const float4* xv = (const float4*)(xyz + (size_t)row*CIN);
    #pragma unroll
    for (int q = 0; q < 16; q++){
        float4 v = xv[q];
        f[4*q]=v.x; f[4*q+1]=v.y; f[4*q+2]=v.z; f[4*q+3]=v.w;
    }
    float acc[HID];
    #pragma unroll
    for (int j = 0; j < HID; j++) acc[j] = bs[j];
    for (int c = 0; c < CIN; c++){
        float a = f[c];
        const float4* w = (const float4*)(Ws + c*HID);
        #pragma unroll
        for (int q = 0; q < 16; q++){
            float4 wv = w[q];
            acc[4*q]   = fmaf(a, wv.x, acc[4*q]);
            acc[4*q+1] = fmaf(a, wv.y, acc[4*q+1]);
            acc[4*q+2] = fmaf(a, wv.z, acc[4*q+2]);
            acc[4*q+3] = fmaf(a, wv.w, acc[4*q+3]);
        }
    }
    float4* o = (float4*)(g_F1 + (size_t)row*HID);
    #pragma unroll
    for (int q = 0; q < 16; q++)
        o[q] = make_float4(acc[4*q], acc[4*q+1], acc[4*q+2], acc[4*q+3]);
}

// ---------------------------------------------------------------------------
// Kernel 3: radius + exact top-K (ties by lower index). One block per center.
// ---------------------------------------------------------------------------
__global__ void __launch_bounds__(128) nbr_kernel(const float* __restrict__ point){
    __shared__ unsigned long long keys[512];
    __shared__ int ncand;
    int c = blockIdx.x, tid = threadIdx.x;
    int b = c >> 10;
    int cl = g_fps[c];
    const float* P = point + (size_t)b*NPP*3;
    float cx = P[cl*3+0], cy = P[cl*3+1], cz = P[cl*3+2];
    if (tid == 0) ncand = 0;
    __syncthreads();

    for (int i = tid; i < NPP; i += 128){
        float d2 = d2f(P[i*3+0], P[i*3+1], P[i*3+2], cx, cy, cz);
        if (d2 < R2){
            int p = atomicAdd(&ncand, 1);
            if (p < 512)
                keys[p] = (((unsigned long long)__float_as_uint(d2)) << 32) | (unsigned)i;
        }
    }
    __syncthreads();
    int n   = min(ncand, 512);
    int cnt = min(n, KK);
    if (tid == 0) g_cnt[c] = cnt;
    for (int i = tid; i < n; i += 128){
        unsigned long long k = keys[i];
        int rank = 0;
        for (int j = 0; j < n; j++) rank += (keys[j] < k);
        if (rank < KK) g_nbr[c*KK + rank] = (int)(k & 0xffffffffu);
    }
    for (int i = cnt + tid; i < KK; i += 128) g_nbr[c*KK + i] = cl;  /* padded, masked later */
}

// ---------------------------------------------------------------------------
// Kernel 4: per-pair MLP (h1 pos-part + relu, h2, h3) + max over K.
// 256 threads = 4 centers x 64 neighbor slots. Weights in SMEM (broadcast).
// ---------------------------------------------------------------------------
__global__ void __launch_bounds__(256,1) mlp_kernel(const float* __restrict__ point,
                                                    const float* __restrict__ W1,
                                                    const float* __restrict__ W2,
                                                    const float* __restrict__ b2,
                                                    const float* __restrict__ W3,
                                                    const float* __restrict__ b3,
                                                    float* __restrict__ out){
    extern __shared__ float sm[];
    float* W2s = sm;            /* 4096 */
    float* W3s = sm + 4096;     /* 8192 */
    float* Wp  = sm + 12288;    /* 192  (W1 rows 64..66) */
    float* b2s = sm + 12480;    /* 64   */
    float* b3s = sm + 12544;    /* 128  */
    float* red = sm + 12672;    /* 4*32 */

    int tid = threadIdx.x, lane = tid & 31;
    for (int i = tid; i < 4096; i += 256) W2s[i] = W2[i];
    for (int i = tid; i < 8192; i += 256) W3s[i] = W3[i];
    if (tid < 192) Wp[tid] = W1[4096 + tid];
    if (tid < 64)  b2s[tid] = b2[tid];
    if (tid < 128) b3s[tid] = b3[tid];
    __syncthreads();

    int ci   = tid >> 6;          /* center in block */
    int ks   = tid & 63;          /* neighbor slot   */
    int half = (tid >> 5) & 1;
    int c    = blockIdx.x*4 + ci;
    int b    = c >> 10;
    int cnt  = g_cnt[c];
    int j    = g_nbr[c*KK + ks];
    int cl   = g_fps[c];
    const float* P = point + (size_t)b*NPP*3;
    float dx = __fsub_rn(P[j*3+0], P[cl*3+0]);
    float dy = __fsub_rn(P[j*3+1], P[cl*3+1]);
    float dz = __fsub_rn(P[j*3+2], P[cl*3+2]);

    /* h1 = relu(F1[j] + dpos @ W1[64:67]) */
    float h1[HID];
    const float4* fv = (const float4*)(g_F1 + (size_t)(b*NPP + j)*HID);
    #pragma unroll
    for (int q = 0; q < 16; q++){
        float4 v = fv[q];
        h1[4*q]=v.x; h1[4*q+1]=v.y; h1[4*q+2]=v.z; h1[4*q+3]=v.w;
    }
    #pragma unroll
    for (int i = 0; i < HID; i++){
        float v = h1[i];
        v = fmaf(dx, Wp[i],      v);
        v = fmaf(dy, Wp[64 + i], v);
        v = fmaf(dz, Wp[128+ i], v);
        h1[i] = fmaxf(v, 0.f);
    }

    /* h2 = relu(h1 @ W2 + b2) */
    float h2[HID];
    #pragma unroll
    for (int i = 0; i < HID; i++) h2[i] = b2s[i];
    for (int cc = 0; cc < HID; cc++){
        float a = h1[cc];
        const float4* w = (const float4*)(W2s + cc*HID);
        #pragma unroll
        for (int q = 0; q < 16; q++){
            float4 wv = w[q];
            h2[4*q]   = fmaf(a, wv.x, h2[4*q]);
            h2[4*q+1] = fmaf(a, wv.y, h2[4*q+1]);
            h2[4*q+2] = fmaf(a, wv.z, h2[4*q+2]);
            h2[4*q+3] = fmaf(a, wv.w, h2[4*q+3]);
        }
    }
    #pragma unroll
    for (int i = 0; i < HID; i++) h2[i] = fmaxf(h2[i], 0.f);

    bool valid = (ks < cnt);

    /* h3 in chunks of 32, relu+mask, max over the 64 slots of the center */
    #pragma unroll
    for (int ch = 0; ch < 4; ch++){
        float o[32];
        #pragma unroll
        for (int q = 0; q < 32; q++) o[q] = b3s[ch*32 + q];
        for (int cc = 0; cc < HID; cc++){
            float a = h2[cc];
            const float4* w = (const float4*)(W3s + cc*OUTD + ch*32);
            #pragma unroll
            for (int q = 0; q < 8; q++){
                float4 wv = w[q];
                o[4*q]   = fmaf(a, wv.x, o[4*q]);
                o[4*q+1] = fmaf(a, wv.y, o[4*q+1]);
                o[4*q+2] = fmaf(a, wv.z, o[4*q+2]);
                o[4*q+3] = fmaf(a, wv.w, o[4*q+3]);
            }
        }
        #pragma unroll
        for (int q = 0; q < 32; q++)
            o[q] = valid ? fmaxf(o[q], 0.f) : -3.402823466e38f;
        #pragma unroll
        for (int s = 16; s; s >>= 1){
            #pragma unroll
            for (int q = 0; q < 32; q++)
                o[q] = fmaxf(o[q], __shfl_xor_sync(0xffffffffu, o[q], s));
        }
        __syncthreads();
        if (half == 1 && lane == 0){
            #pragma unroll
            for (int q = 0; q < 32; q++) red[ci*32 + q] = o[q];
        }
        __syncthreads();
        if (half == 0 && lane == 0){
            #pragma unroll
            for (int q = 0; q < 32; q++)
                out[(size_t)c*OUTD + ch*32 + q] = fmaxf(o[q], red[ci*32 + q]);
        }
    }
}

// ---------------------------------------------------------------------------
// Kernel 5: centers + batch output segments.
// ---------------------------------------------------------------------------
__global__ void aux_kernel(const float* __restrict__ point, float* __restrict__ out){
    int t = blockIdx.x*blockDim.x + threadIdx.x;
    if (t < NC){
        int b  = t >> 10;
        int gi = b*NPP + g_fps[t];
        out[OFF_C + t*3 + 0] = point[gi*3 + 0];
        out[OFF_C + t*3 + 1] = point[gi*3 + 1];
        out[OFF_C + t*3 + 2] = point[gi*3 + 2];
        out[OFF_B + t] = (float)b;
    }
}

extern "C" void kernel_launch(void* const* d_in, const int* in_sizes, int n_in,
                              void* d_out, int out_size){
    const float *xyz=nullptr, *point=nullptr, *W1=nullptr, *b1=nullptr,
                *W2=nullptr, *b2=nullptr, *W3=nullptr, *b3=nullptr;
    int n64 = 0;
    for (int i = 0; i < n_in; i++){
        switch (in_sizes[i]){
            case 4194304: xyz   = (const float*)d_in[i]; break;
            case 196608:  point = (const float*)d_in[i]; break;
            case 4288:    W1    = (const float*)d_in[i]; break;
            case 4096:    W2    = (const float*)d_in[i]; break;
            case 8192:    W3    = (const float*)d_in[i]; break;
            case 64:      if (n64++ == 0) b1 = (const float*)d_in[i];
                          else            b2 = (const float*)d_in[i]; break;
            case 128:     b3    = (const float*)d_in[i]; break;
            default: break;
        }
    }
    float* out = (float*)d_out;

    cudaFuncSetAttribute(fps_kernel, cudaFuncAttributeMaxDynamicSharedMemorySize,
                         4*NPP*(int)sizeof(float));
    cudaFuncSetAttribute(mlp_kernel, cudaFuncAttributeMaxDynamicSharedMemorySize,
                         12800*(int)sizeof(float));

    fps_kernel<<<BB, 1024, 4*NPP*sizeof(float)>>>(point);
    f1_kernel<<<BB*NPP/256, 256>>>(xyz, W1, b1);
    nbr_kernel<<<NC, 128>>>(point);
    mlp_kernel<<<NC/4, 256, 12800*sizeof(float)>>>(point, W1, W2, b2, W3, b3, out);
    aux_kernel<<<(NC+255)/256, 256>>>(point, out);
}

// round 2
// speedup vs baseline: 1.4242x; 1.4242x over previous
#include <cuda_runtime.h>
#include <cstdint>

#define BB   16
#define NPP  4096
#define CIN  64
#define MM   1024
#define KK   64
#define HID  64
#define OUTD 128
#define NC   (BB*MM)
#define R2   0.04f

#define OFF_C 2097152         /* NC*OUTD */
#define OFF_B 2146304         /* OFF_C + NC*3 */

__device__ int   g_fps[NC];
__device__ int   g_nbr[NC*KK];
__device__ int   g_cnt[NC];
__device__ float g_F1[(size_t)BB*NPP*HID];

__device__ __forceinline__ float d2f(float ax,float ay,float az,float bx,float by,float bz){
    float dx=__fsub_rn(ax,bx), dy=__fsub_rn(ay,by), dz=__fsub_rn(az,bz);
    return __fadd_rn(__fadd_rn(__fmul_rn(dx,dx),__fmul_rn(dy,dy)),__fmul_rn(dz,dz));
}

/* ---- packed fp32x2 helpers (sm_103a FFMA2 — ptxas never emits it itself) ---- */
__device__ __forceinline__ void fma2(unsigned long long &d, unsigned long long a, unsigned long long b){
    asm("fma.rn.f32x2 %0, %1, %2, %0;" : "+l"(d) : "l"(a), "l"(b));
}
__device__ __forceinline__ unsigned long long splat2(float x){
    unsigned long long r; unsigned u = __float_as_uint(x);
    asm("mov.b64 %0, {%1, %1};" : "=l"(r) : "r"(u)); return r;
}
__device__ __forceinline__ void unpack2(unsigned long long v, float &lo, float &hi){
    unsigned a,b; asm("mov.b64 {%0, %1}, %2;" : "=r"(a), "=r"(b) : "l"(v));
    lo = __uint_as_float(a); hi = __uint_as_float(b);
}
__device__ __forceinline__ unsigned long long pack2(float lo, float hi){
    unsigned long long r;
    asm("mov.b64 %0, {%1, %2};" : "=l"(r) : "r"(__float_as_uint(lo)), "r"(__float_as_uint(hi)));
    return r;
}

// ---------------------------------------------------------------------------
// Kernel 1: fused FPS (blocks 0..15) + F1 precompute (blocks 16..143).
// FPS: 512 threads, one barrier per iteration (double-buffered warp partials).
// F1:  F1[row] = xyz[row] @ W1[:64] + b1, one row per thread.
// ---------------------------------------------------------------------------
__global__ void __launch_bounds__(512,1) fpsf1_kernel(const float* __restrict__ point,
                                                      const float* __restrict__ xyz,
                                                      const float* __restrict__ W1,
                                                      const float* __restrict__ b1){
    extern __shared__ float sm[];
    int tid = threadIdx.x, lane = tid & 31, warp = tid >> 5;

    if (blockIdx.x < BB){
        float* px = sm;
        float* py = sm +   NPP;
        float* pz = sm + 2*NPP;
        float* dd = sm + 3*NPP;
        __shared__ float wv[2][16];
        __shared__ int   wi[2][16];

        int b = blockIdx.x;
        const float* P = point + (size_t)b*NPP*3;
        for (int i = tid; i < NPP; i += 512){
            px[i] = P[i*3+0]; py[i] = P[i*3+1]; pz[i] = P[i*3+2];
            dd[i] = 3.402823466e38f;
        }
        if (tid == 0) g_fps[b*MM] = 0;
        __syncthreads();

        int last = 0;
        for (int m = 1; m < MM; m++){
            float cx = px[last], cy = py[last], cz = pz[last];
            float bv = -1.f; int bi = NPP;
            #pragma unroll
            for (int r = 0; r < 8; r++){
                int i = tid + r*512;
                float nd = d2f(px[i], py[i], pz[i], cx, cy, cz);
                float v  = fminf(dd[i], nd);
                dd[i] = v;
                if (v > bv || (v == bv && i < bi)){ bv = v; bi = i; }
            }
            #pragma unroll
            for (int s = 16; s; s >>= 1){
                float ov = __shfl_xor_sync(0xffffffffu, bv, s);
                int   oi = __shfl_xor_sync(0xffffffffu, bi, s);
                if (ov > bv || (ov == bv && oi < bi)){ bv = ov; bi = oi; }
            }
            int par = m & 1;
            if (lane == 0){ wv[par][warp] = bv; wi[par][warp] = bi; }
            __syncthreads();
            float fv = wv[par][lane & 15];
            int   fi = wi[par][lane & 15];
            #pragma unroll
            for (int s = 8; s; s >>= 1){
                float ov = __shfl_xor_sync(0xffffffffu, fv, s);
                int   oi = __shfl_xor_sync(0xffffffffu, fi, s);
                if (ov > fv || (ov == fv && oi < fi)){ fv = ov; fi = oi; }
            }
            last = fi;
            if (tid == 0) g_fps[b*MM + m] = last;
        }
    } else {
        float* W1s = sm;          /* 4096 */
        float* b1s = sm + 4096;   /* 64   */
        for (int i = tid; i < CIN*HID; i += 512) W1s[i] = W1[i];
        if (tid < HID) b1s[tid] = b1[tid];
        __syncthreads();

        int row = (blockIdx.x - BB)*512 + tid;
        float acc[HID];
        #pragma unroll
        for (int o = 0; o < HID; o++) acc[o] = b1s[o];
        const float4* xr = (const float4*)(xyz + (size_t)row*CIN);
        #pragma unroll
        for (int q = 0; q < 16; q++){
            float4 xv = xr[q];
            float av[4] = {xv.x, xv.y, xv.z, xv.w};
            #pragma unroll
            for (int t = 0; t < 4; t++){
                float a = av[t];
                const float4* w = (const float4*)(W1s + (q*4+t)*HID);
                #pragma unroll
                for (int u = 0; u < 16; u++){
                    float4 wv4 = w[u];
                    acc[4*u]   = fmaf(a, wv4.x, acc[4*u]);
                    acc[4*u+1] = fmaf(a, wv4.y, acc[4*u+1]);
                    acc[4*u+2] = fmaf(a, wv4.z, acc[4*u+2]);
                    acc[4*u+3] = fmaf(a, wv4.w, acc[4*u+3]);
                }
            }
        }
        float4* o4 = (float4*)(g_F1 + (size_t)row*HID);
        #pragma unroll
        for (int u = 0; u < 16; u++)
            o4[u] = make_float4(acc[4*u], acc[4*u+1], acc[4*u+2], acc[4*u+3]);
    }
}

// ---------------------------------------------------------------------------
// Kernel 2: radius + exact top-K (ties by lower index). One block per center.
// ---------------------------------------------------------------------------
__global__ void __launch_bounds__(128) nbr_kernel(const float* __restrict__ point){
    __shared__ unsigned long long keys[512];
    __shared__ int ncand;
    int c = blockIdx.x, tid = threadIdx.x;
    int b = c >> 10;
    int cl = g_fps[c];
    const float* P = point + (size_t)b*NPP*3;
    float cx = P[cl*3+0], cy = P[cl*3+1], cz = P[cl*3+2];
    if (tid == 0) ncand = 0;
    __syncthreads();

    for (int i = tid; i < NPP; i += 128){
        float d2 = d2f(P[i*3+0], P[i*3+1], P[i*3+2], cx, cy, cz);
        if (d2 < R2){
            int p = atomicAdd(&ncand, 1);
            if (p < 512)
                keys[p] = (((unsigned long long)__float_as_uint(d2)) << 32) | (unsigned)i;
        }
    }
    __syncthreads();
    int n   = min(ncand, 512);
    int cnt = min(n, KK);
    if (tid == 0) g_cnt[c] = cnt;
    for (int i = tid; i < n; i += 128){
        unsigned long long k = keys[i];
        int rank = 0;
        for (int j = 0; j < n; j++) rank += (keys[j] < k);
        if (rank < KK) g_nbr[c*KK + rank] = (int)(k & 0xffffffffu);
    }
    for (int i = cnt + tid; i < KK; i += 128) g_nbr[c*KK + i] = cl;
}

// ---------------------------------------------------------------------------
// Kernel 3: MLP as register-tiled smem GEMM with packed FFMA2.
// Block = 256 pairs (4 centers). Activations staged transposed [k][256].
// Thread tile: 4 pair-pairs (f32x2) x 8 outs = 64 fp32 accumulators.
// ---------------------------------------------------------------------------
__global__ void __launch_bounds__(256,1) mlp_kernel(const float* __restrict__ point,
                                                    const float* __restrict__ W1,
                                                    const float* __restrict__ W2,
                                                    const float* __restrict__ b2,
                                                    const float* __restrict__ W3,
                                                    const float* __restrict__ b3,
                                                    float* __restrict__ out){
    extern __shared__ float sm[];
    float* buf  = sm;            /* 16384 : [64][256] activations (h1, then h2) */
    float* W2s  = sm + 16384;    /* 4096  */
    float* W3s  = sm + 20480;    /* 8192  */
    float* Wp   = sm + 28672;    /* 192   : W1 rows 64..66 */
    float* b2s  = sm + 28864;    /* 64    */
    float* b3s  = sm + 28928;    /* 128   */

    int tid = threadIdx.x, lane = tid & 31, wid = tid >> 5;
    for (int i = tid; i < 4096; i += 256) W2s[i] = W2[i];
    for (int i = tid; i < 8192; i += 256) W3s[i] = W3[i];
    if (tid < 192) Wp[tid]  = W1[4096 + tid];
    if (tid < 64)  b2s[tid] = b2[tid];
    if (tid < 128) b3s[tid] = b3[tid];

    int c0 = blockIdx.x*4;
    int b  = c0 >> 10;
    const float* P = point + (size_t)b*NPP*3;

    /* ---- stage A: h1 for pair p = tid, written transposed into buf ---- */
    int p    = tid;
    int ci   = p >> 6;
    int cl   = g_fps[c0 + ci];
    int j    = g_nbr[blockIdx.x*256 + p];
    __syncthreads();   /* Wp ready before use */

    float dx = __fsub_rn(P[j*3+0], P[cl*3+0]);
    float dy = __fsub_rn(P[j*3+1], P[cl*3+1]);
    float dz = __fsub_rn(P[j*3+2], P[cl*3+2]);

    float h1[HID];
    const float4* fv = (const float4*)(g_F1 + (size_t)(b*NPP + j)*HID);
    #pragma unroll
    for (int q = 0; q < 16; q++){
        float4 v = fv[q];
        h1[4*q]=v.x; h1[4*q+1]=v.y; h1[4*q+2]=v.z; h1[4*q+3]=v.w;
    }
    #pragma unroll
    for (int i = 0; i < HID; i++){
        float v = h1[i];
        v = fmaf(dx, Wp[i],       v);
        v = fmaf(dy, Wp[64 + i],  v);
        v = fmaf(dz, Wp[128 + i], v);
        h1[i] = fmaxf(v, 0.f);
    }
    #pragma unroll
    for (int k = 0; k < HID; k++) buf[k*256 + tid] = h1[k];
    __syncthreads();

    int ow = wid*8;   /* this warp's 8-output chunk */

    /* ---- stage B: h2 = relu(h1 @ W2 + b2), tiled, FFMA2 ---- */
    {
        unsigned long long acc[4][8];
        #pragma unroll
        for (int o = 0; o < 8; o++){
            unsigned long long bv = splat2(b2s[ow + o]);
            #pragma unroll
            for (int i = 0; i < 4; i++) acc[i][o] = bv;
        }
        const float* bptr = buf + 2*lane;
        #pragma unroll 4
        for (int k = 0; k < HID; k++){
            unsigned long long A2[4];
            #pragma unroll
            for (int i = 0; i < 4; i++)
                A2[i] = *(const unsigned long long*)(bptr + k*256 + 64*i);
            float4 w0 = *(const float4*)(W2s + k*64 + ow);
            float4 w1 = *(const float4*)(W2s + k*64 + ow + 4);
            unsigned long long B2[8] = { splat2(w0.x), splat2(w0.y), splat2(w0.z), splat2(w0.w),
                                         splat2(w1.x), splat2(w1.y), splat2(w1.z), splat2(w1.w) };
            #pragma unroll
            for (int o = 0; o < 8; o++)
                #pragma unroll
                for (int i = 0; i < 4; i++)
                    fma2(acc[i][o], A2[i], B2[o]);
        }
        __syncthreads();   /* all reads of h1 done, reuse buf for h2 */
        #pragma unroll
        for (int o = 0; o < 8; o++)
            #pragma unroll
            for (int i = 0; i < 4; i++){
                float lo, hi; unpack2(acc[i][o], lo, hi);
                *(unsigned long long*)(buf + (ow+o)*256 + 2*lane + 64*i) =
                    pack2(fmaxf(lo, 0.f), fmaxf(hi, 0.f));
            }
        __syncthreads();
    }

    /* ---- stage C/D: h3 = relu(h2 @ W3 + b3), mask, max over 64 slots ---- */
    int cnt4[4];
    #pragma unroll
    for (int i = 0; i < 4; i++) cnt4[i] = g_cnt[c0 + i];

    #pragma unroll
    for (int pass = 0; pass < 2; pass++){
        unsigned long long acc[4][8];
        #pragma unroll
        for (int o = 0; o < 8; o++){
            unsigned long long bv = splat2(b3s[pass*64 + ow + o]);
            #pragma unroll
            for (int i = 0; i < 4; i++) acc[i][o] = bv;
        }
        const float* bptr = buf + 2*lane;
        #pragma unroll 4
        for (int k = 0; k < HID; k++){
            unsigned long long A2[4];
            #pragma unroll
            for (int i = 0; i < 4; i++)
                A2[i] = *(const unsigned long long*)(bptr + k*256 + 64*i);
            const float* w = W3s + k*128 + pass*64 + ow;
            float4 w0 = *(const float4*)(w);
            float4 w1 = *(const float4*)(w + 4);
            unsigned long long B2[8] = { splat2(w0.x), splat2(w0.y), splat2(w0.z), splat2(w0.w),
                                         splat2(w1.x), splat2(w1.y), splat2(w1.z), splat2(w1.w) };
            #pragma unroll
            for (int o = 0; o < 8; o++)
                #pragma unroll
                for (int i = 0; i < 4; i++)
                    fma2(acc[i][o], A2[i], B2[o]);
        }
        /* masked relu + max over the 2 packed slots, then warp butterfly */
        #pragma unroll
        for (int i = 0; i < 4; i++){
            bool v0 = (2*lane)     < cnt4[i];
            bool v1 = (2*lane + 1) < cnt4[i];
            #pragma unroll
            for (int o = 0; o < 8; o++){
                float lo, hi; unpack2(acc[i][o], lo, hi);
                lo = v0 ? fmaxf(lo, 0.f) : -3.402823466e38f;
                hi = v1 ? fmaxf(hi, 0.f) : -3.402823466e38f;
                float m = fmaxf(lo, hi);
                #pragma unroll
                for (int s = 16; s; s >>= 1)
                    m = fmaxf(m, __shfl_xor_sync(0xffffffffu, m, s));
                if (lane == 0)
                    out[(size_t)(c0 + i)*OUTD + pass*64 + ow + o] = m;
            }
        }
    }
}

// ---------------------------------------------------------------------------
// Kernel 4: centers + batch output segments.
// ---------------------------------------------------------------------------
__global__ void aux_kernel(const float* __restrict__ point, float* __restrict__ out){
    int t = blockIdx.x*blockDim.x + threadIdx.x;
    if (t < NC){
        int b  = t >> 10;
        int gi = b*NPP + g_fps[t];
        out[OFF_C + t*3 + 0] = point[gi*3 + 0];
        out[OFF_C + t*3 + 1] = point[gi*3 + 1];
        out[OFF_C + t*3 + 2] = point[gi*3 + 2];
        out[OFF_B + t] = (float)b;
    }
}

extern "C" void kernel_launch(void* const* d_in, const int* in_sizes, int n_in,
                              void* d_out, int out_size){
    const float *xyz=nullptr, *point=nullptr, *W1=nullptr, *b1=nullptr,
                *W2=nullptr, *b2=nullptr, *W3=nullptr, *b3=nullptr;
    int n64 = 0;
    for (int i = 0; i < n_in; i++){
        switch (in_sizes[i]){
            case 4194304: xyz   = (const float*)d_in[i]; break;
            case 196608:  point = (const float*)d_in[i]; break;
            case 4288:    W1    = (const float*)d_in[i]; break;
            case 4096:    W2    = (const float*)d_in[i]; break;
            case 8192:    W3    = (const float*)d_in[i]; break;
            case 64:      if (n64++ == 0) b1 = (const float*)d_in[i];
                          else            b2 = (const float*)d_in[i]; break;
            case 128:     b3    = (const float*)d_in[i]; break;
            default: break;
        }
    }
    float* out = (float*)d_out;

    cudaFuncSetAttribute(fpsf1_kernel, cudaFuncAttributeMaxDynamicSharedMemorySize,
                         4*NPP*(int)sizeof(float));
    cudaFuncSetAttribute(mlp_kernel, cudaFuncAttributeMaxDynamicSharedMemorySize,
                         29056*(int)sizeof(float));

    fpsf1_kernel<<<BB + BB*NPP/512, 512, 4*NPP*sizeof(float)>>>(point, xyz, W1, b1);
    nbr_kernel<<<NC, 128>>>(point);
    mlp_kernel<<<NC/4, 256, 29056*sizeof(float)>>>(point, W1, W2, b2, W3, b3, out);
    aux_kernel<<<(NC+255)/256, 256>>>(point, out);
}

// round 3
// speedup vs baseline: 1.9977x; 1.4027x over previous
#include <cuda_runtime.h>
#include <cstdint>

#define BB   16
#define NPP  4096
#define CIN  64
#define MM   1024
#define KK   64
#define HID  64
#define OUTD 128
#define NC   (BB*MM)
#define R2   0.04f

#define OFF_C 2097152         /* NC*OUTD */
#define OFF_B 2146304         /* OFF_C + NC*3 */

__device__ int   g_fps[NC];
__device__ int   g_nbr[NC*KK];
__device__ int   g_cnt[NC];
__device__ float g_F1[(size_t)BB*NPP*HID];

__device__ __forceinline__ float d2f(float ax,float ay,float az,float bx,float by,float bz){
    float dx=__fsub_rn(ax,bx), dy=__fsub_rn(ay,by), dz=__fsub_rn(az,bz);
    return __fadd_rn(__fadd_rn(__fmul_rn(dx,dx),__fmul_rn(dy,dy)),__fmul_rn(dz,dz));
}

/* ---- packed fp32x2 helpers (sm_103a FFMA2) ---- */
__device__ __forceinline__ void fma2(unsigned long long &d, unsigned long long a, unsigned long long b){
    asm("fma.rn.f32x2 %0, %1, %2, %0;" : "+l"(d) : "l"(a), "l"(b));
}
__device__ __forceinline__ unsigned long long splat2(float x){
    unsigned long long r; unsigned u = __float_as_uint(x);
    asm("mov.b64 %0, {%1, %1};" : "=l"(r) : "r"(u)); return r;
}
__device__ __forceinline__ void unpack2(unsigned long long v, float &lo, float &hi){
    unsigned a,b; asm("mov.b64 {%0, %1}, %2;" : "=r"(a), "=r"(b) : "l"(v));
    lo = __uint_as_float(a); hi = __uint_as_float(b);
}
__device__ __forceinline__ unsigned long long pack2(float lo, float hi){
    unsigned long long r;
    asm("mov.b64 %0, {%1, %2};" : "=l"(r) : "r"(__float_as_uint(lo)), "r"(__float_as_uint(hi)));
    return r;
}

// ---------------------------------------------------------------------------
// Kernel 1: fused FPS (blocks 0..15, register-resident) + F1 (blocks 16..143).
// ---------------------------------------------------------------------------
__global__ void __launch_bounds__(1024,1) fpsf1_kernel(const float* __restrict__ point,
                                                       const float* __restrict__ xyz,
                                                       const float* __restrict__ W1,
                                                       const float* __restrict__ b1){
    extern __shared__ float sm[];
    int tid = threadIdx.x, lane = tid & 31, warp = tid >> 5;

    if (blockIdx.x < BB){
        float* px = sm;
        float* py = sm +   NPP;
        float* pz = sm + 2*NPP;
        __shared__ unsigned wbS[32];
        __shared__ unsigned wiS[32];
        __shared__ int selS;

        int b = blockIdx.x;
        const float* P = point + (size_t)b*NPP*3;
        float x[4], y[4], z[4], d[4];
        #pragma unroll
        for (int r = 0; r < 4; r++){
            int i = tid + r*1024;
            float a0 = P[i*3+0], a1 = P[i*3+1], a2 = P[i*3+2];
            px[i] = a0; py[i] = a1; pz[i] = a2;
            x[r] = a0; y[r] = a1; z[r] = a2;
            d[r] = 3.402823466e38f;
        }
        if (tid == 0) g_fps[b*MM] = 0;
        __syncthreads();

        int last = 0;
        for (int m = 1; m < MM; m++){
            float cx = px[last], cy = py[last], cz = pz[last];
            unsigned bestb = 0u; int besti = NPP;
            #pragma unroll
            for (int r = 0; r < 4; r++){
                float nd = d2f(x[r], y[r], z[r], cx, cy, cz);
                float v  = fminf(d[r], nd);
                d[r] = v;
                unsigned vb = __float_as_uint(v);       /* v >= 0: bits monotonic */
                int i = tid + r*1024;
                if (vb > bestb || (vb == bestb && i < besti)){ bestb = vb; besti = i; }
            }
            unsigned wmax = __reduce_max_sync(0xffffffffu, bestb);
            unsigned cand = (bestb == wmax) ? (unsigned)besti : 0xffffffffu;
            unsigned widx = __reduce_min_sync(0xffffffffu, cand);
            if (lane == 0){ wbS[warp] = wmax; wiS[warp] = widx; }
            __syncthreads();
            if (warp == 0){
                unsigned b2 = wbS[lane], i2 = wiS[lane];
                unsigned gmax = __reduce_max_sync(0xffffffffu, b2);
                unsigned c2   = (b2 == gmax) ? i2 : 0xffffffffu;
                unsigned gidx = __reduce_min_sync(0xffffffffu, c2);
                if (lane == 0){ selS = (int)gidx; g_fps[b*MM + m] = (int)gidx; }
            }
            __syncthreads();
            last = selS;
        }
    } else {
        /* F1: 2 threads per row, 32 outputs each */
        float* W1s = sm;          /* 4096 */
        float* b1s = sm + 4096;   /* 64   */
        for (int i = tid; i < CIN*HID; i += 1024) W1s[i] = W1[i];
        if (tid < HID) b1s[tid] = b1[tid];
        __syncthreads();

        int row  = (blockIdx.x - BB)*512 + (tid >> 1);
        int half = tid & 1;
        float acc[32];
        #pragma unroll
        for (int o = 0; o < 32; o++) acc[o] = b1s[half*32 + o];
        const float4* xr = (const float4*)(xyz + (size_t)row*CIN);
        #pragma unroll
        for (int q = 0; q < 16; q++){
            float4 xv = xr[q];
            float av[4] = {xv.x, xv.y, xv.z, xv.w};
            #pragma unroll
            for (int t = 0; t < 4; t++){
                float a = av[t];
                const float4* w = (const float4*)(W1s + (q*4+t)*HID + half*32);
                #pragma unroll
                for (int u = 0; u < 8; u++){
                    float4 wv4 = w[u];
                    acc[4*u]   = fmaf(a, wv4.x, acc[4*u]);
                    acc[4*u+1] = fmaf(a, wv4.y, acc[4*u+1]);
                    acc[4*u+2] = fmaf(a, wv4.z, acc[4*u+2]);
                    acc[4*u+3] = fmaf(a, wv4.w, acc[4*u+3]);
                }
            }
        }
        float4* o4 = (float4*)(g_F1 + (size_t)row*HID + half*32);
        #pragma unroll
        for (int u = 0; u < 8; u++)
            o4[u] = make_float4(acc[4*u], acc[4*u+1], acc[4*u+2], acc[4*u+3]);
    }
}

// ---------------------------------------------------------------------------
// Kernel 2: radius + exact top-K. One block serves 16 centers of one cloud,
// points staged in smem once.
// ---------------------------------------------------------------------------
__global__ void __launch_bounds__(256) nbr_kernel(const float* __restrict__ point){
    extern __shared__ float sm[];
    float* px = sm;
    float* py = sm +   NPP;
    float* pz = sm + 2*NPP;
    unsigned long long* keys = (unsigned long long*)(sm + 3*NPP);  /* 512 */
    __shared__ int ncand[16];

    int tid = threadIdx.x;
    int c0  = blockIdx.x*16;
    int b   = c0 >> 10;
    const float* P = point + (size_t)b*NPP*3;
    for (int i = tid; i < NPP; i += 256){
        px[i] = P[i*3+0]; py[i] = P[i*3+1]; pz[i] = P[i*3+2];
    }
    if (tid < 16) ncand[tid] = 0;
    __syncthreads();

    for (int ci = 0; ci < 16; ci++){
        int c  = c0 + ci;
        int cl = g_fps[c];
        float cx = px[cl], cy = py[cl], cz = pz[cl];
        for (int i = tid; i < NPP; i += 256){
            float d2 = d2f(px[i], py[i], pz[i], cx, cy, cz);
            if (d2 < R2){
                int p = atomicAdd(&ncand[ci], 1);
                if (p < 512)
                    keys[p] = (((unsigned long long)__float_as_uint(d2)) << 32) | (unsigned)i;
            }
        }
        __syncthreads();
        int n   = min(ncand[ci], 512);
        int cnt = min(n, KK);
        if (tid == 0) g_cnt[c] = cnt;
        for (int i = tid; i < n; i += 256){
            unsigned long long k = keys[i];
            int rank = 0;
            for (int j = 0; j < n; j++) rank += (keys[j] < k);
            if (rank < KK) g_nbr[c*KK + rank] = (int)(k & 0xffffffffu);
        }
        for (int i = cnt + tid; i < KK; i += 256) g_nbr[c*KK + i] = cl;
        __syncthreads();  /* keys reads done before next center overwrites */
    }
}

// ---------------------------------------------------------------------------
// Kernel 3: MLP, register-tiled FFMA2 GEMM. W3 from global (L1) -> 2 blocks/SM.
// ---------------------------------------------------------------------------
__global__ void __launch_bounds__(256,2) mlp_kernel(const float* __restrict__ point,
                                                    const float* __restrict__ W1,
                                                    const float* __restrict__ W2,
                                                    const float* __restrict__ b2,
                                                    const float* __restrict__ W3,
                                                    const float* __restrict__ b3,
                                                    float* __restrict__ out){
    extern __shared__ float sm[];
    float* buf  = sm;            /* 16384 : [64][256] activations (h1, then h2) */
    float* W2s  = sm + 16384;    /* 4096  */
    float* Wp   = sm + 20480;    /* 192   */
    float* b2s  = sm + 20672;    /* 64    */
    float* b3s  = sm + 20736;    /* 128   */

    int tid = threadIdx.x, lane = tid & 31, wid = tid >> 5;
    for (int i = tid; i < 4096; i += 256) W2s[i] = W2[i];
    if (tid < 192) Wp[tid]  = W1[4096 + tid];
    if (tid < 64)  b2s[tid] = b2[tid];
    if (tid < 128) b3s[tid] = b3[tid];

    int c0 = blockIdx.x*4;
    int b  = c0 >> 10;
    const float* P = point + (size_t)b*NPP*3;

    int ci   = tid >> 6;
    int cl   = g_fps[c0 + ci];
    int j    = g_nbr[blockIdx.x*256 + tid];
    __syncthreads();

    float dx = __fsub_rn(P[j*3+0], P[cl*3+0]);
    float dy = __fsub_rn(P[j*3+1], P[cl*3+1]);
    float dz = __fsub_rn(P[j*3+2], P[cl*3+2]);

    float h1[HID];
    const float4* fv = (const float4*)(g_F1 + (size_t)(b*NPP + j)*HID);
    #pragma unroll
    for (int q = 0; q < 16; q++){
        float4 v = fv[q];
        h1[4*q]=v.x; h1[4*q+1]=v.y; h1[4*q+2]=v.z; h1[4*q+3]=v.w;
    }
    #pragma unroll
    for (int i = 0; i < HID; i++){
        float v = h1[i];
        v = fmaf(dx, Wp[i],       v);
        v = fmaf(dy, Wp[64 + i],  v);
        v = fmaf(dz, Wp[128 + i], v);
        h1[i] = fmaxf(v, 0.f);
    }
    #pragma unroll
    for (int k = 0; k < HID; k++) buf[k*256 + tid] = h1[k];
    __syncthreads();

    int ow = wid*8;

    /* h2 = relu(h1 @ W2 + b2) */
    {
        unsigned long long acc[4][8];
        #pragma unroll
        for (int o = 0; o < 8; o++){
            unsigned long long bv = splat2(b2s[ow + o]);
            #pragma unroll
            for (int i = 0; i < 4; i++) acc[i][o] = bv;
        }
        const float* bptr = buf + 2*lane;
        #pragma unroll 4
        for (int k = 0; k < HID; k++){
            unsigned long long A2[4];
            #pragma unroll
            for (int i = 0; i < 4; i++)
                A2[i] = *(const unsigned long long*)(bptr + k*256 + 64*i);
            float4 w0 = *(const float4*)(W2s + k*64 + ow);
            float4 w1 = *(const float4*)(W2s + k*64 + ow + 4);
            unsigned long long B2[8] = { splat2(w0.x), splat2(w0.y), splat2(w0.z), splat2(w0.w),
                                         splat2(w1.x), splat2(w1.y), splat2(w1.z), splat2(w1.w) };
            #pragma unroll
            for (int o = 0; o < 8; o++)
                #pragma unroll
                for (int i = 0; i < 4; i++)
                    fma2(acc[i][o], A2[i], B2[o]);
        }
        __syncthreads();
        #pragma unroll
        for (int o = 0; o < 8; o++)
            #pragma unroll
            for (int i = 0; i < 4; i++){
                float lo, hi; unpack2(acc[i][o], lo, hi);
                *(unsigned long long*)(buf + (ow+o)*256 + 2*lane + 64*i) =
                    pack2(fmaxf(lo, 0.f), fmaxf(hi, 0.f));
            }
        __syncthreads();
    }

    int cnt4[4];
    #pragma unroll
    for (int i = 0; i < 4; i++) cnt4[i] = g_cnt[c0 + i];

    #pragma unroll
    for (int pass = 0; pass < 2; pass++){
        unsigned long long acc[4][8];
        #pragma unroll
        for (int o = 0; o < 8; o++){
            unsigned long long bv = splat2(b3s[pass*64 + ow + o]);
            #pragma unroll
            for (int i = 0; i < 4; i++) acc[i][o] = bv;
        }
        const float* bptr = buf + 2*lane;
        #pragma unroll 4
        for (int k = 0; k < HID; k++){
            unsigned long long A2[4];
            #pragma unroll
            for (int i = 0; i < 4; i++)
                A2[i] = *(const unsigned long long*)(bptr + k*256 + 64*i);
            const float* w = W3 + k*128 + pass*64 + ow;   /* global, L1-resident */
            float4 w0 = *(const float4*)(w);
            float4 w1 = *(const float4*)(w + 4);
            unsigned long long B2[8] = { splat2(w0.x), splat2(w0.y), splat2(w0.z), splat2(w0.w),
                                         splat2(w1.x), splat2(w1.y), splat2(w1.z), splat2(w1.w) };
            #pragma unroll
            for (int o = 0; o < 8; o++)
                #pragma unroll
                for (int i = 0; i < 4; i++)
                    fma2(acc[i][o], A2[i], B2[o]);
        }
        #pragma unroll
        for (int i = 0; i < 4; i++){
            bool v0 = (2*lane)     < cnt4[i];
            bool v1 = (2*lane + 1) < cnt4[i];
            #pragma unroll
            for (int o = 0; o < 8; o++){
                float lo, hi; unpack2(acc[i][o], lo, hi);
                lo = v0 ? fmaxf(lo, 0.f) : -3.402823466e38f;
                hi = v1 ? fmaxf(hi, 0.f) : -3.402823466e38f;
                float m = fmaxf(lo, hi);
                #pragma unroll
                for (int s = 16; s; s >>= 1)
                    m = fmaxf(m, __shfl_xor_sync(0xffffffffu, m, s));
                if (lane == 0)
                    out[(size_t)(c0 + i)*OUTD + pass*64 + ow + o] = m;
            }
        }
    }
}

// ---------------------------------------------------------------------------
// Kernel 4: centers + batch output segments.
// ---------------------------------------------------------------------------
__global__ void aux_kernel(const float* __restrict__ point, float* __restrict__ out){
    int t = blockIdx.x*blockDim.x + threadIdx.x;
    if (t < NC){
        int b  = t >> 10;
        int gi = b*NPP + g_fps[t];
        out[OFF_C + t*3 + 0] = point[gi*3 + 0];
        out[OFF_C + t*3 + 1] = point[gi*3 + 1];
        out[OFF_C + t*3 + 2] = point[gi*3 + 2];
        out[OFF_B + t] = (float)b;
    }
}

extern "C" void kernel_launch(void* const* d_in, const int* in_sizes, int n_in,
                              void* d_out, int out_size){
    const float *xyz=nullptr, *point=nullptr, *W1=nullptr, *b1=nullptr,
                *W2=nullptr, *b2=nullptr, *W3=nullptr, *b3=nullptr;
    int n64 = 0;
    for (int i = 0; i < n_in; i++){
        switch (in_sizes[i]){
            case 4194304: xyz   = (const float*)d_in[i]; break;
            case 196608:  point = (const float*)d_in[i]; break;
            case 4288:    W1    = (const float*)d_in[i]; break;
            case 4096:    W2    = (const float*)d_in[i]; break;
            case 8192:    W3    = (const float*)d_in[i]; break;
            case 64:      if (n64++ == 0) b1 = (const float*)d_in[i];
                          else            b2 = (const float*)d_in[i]; break;
            case 128:     b3    = (const float*)d_in[i]; break;
            default: break;
        }
    }
    float* out = (float*)d_out;

    int fps_smem = 3*NPP*(int)sizeof(float);                       /* 48KB  */
    int nbr_smem = 3*NPP*(int)sizeof(float) + 512*8 + 16;          /* ~52KB */
    int mlp_smem = 20864*(int)sizeof(float);                       /* ~82KB */
    cudaFuncSetAttribute(fpsf1_kernel, cudaFuncAttributeMaxDynamicSharedMemorySize, fps_smem);
    cudaFuncSetAttribute(nbr_kernel,   cudaFuncAttributeMaxDynamicSharedMemorySize, nbr_smem);
    cudaFuncSetAttribute(mlp_kernel,   cudaFuncAttributeMaxDynamicSharedMemorySize, mlp_smem);

    fpsf1_kernel<<<BB + BB*NPP/512, 1024, fps_smem>>>(point, xyz, W1, b1);
    nbr_kernel<<<NC/16, 256, nbr_smem>>>(point);
    mlp_kernel<<<NC/4, 256, mlp_smem>>>(point, W1, W2, b2, W3, b3, out);
    aux_kernel<<<(NC+255)/256, 256>>>(point, out);
}

// round 4
// speedup vs baseline: 2.0763x; 1.0394x over previous
#include <cuda_runtime.h>
#include <cstdint>

#define BB   16
#define NPP  4096
#define CIN  64
#define MM   1024
#define KK   64
#define HID  64
#define OUTD 128
#define NC   (BB*MM)
#define R2   0.04f

#define OFF_C 2097152         /* NC*OUTD */
#define OFF_B 2146304         /* OFF_C + NC*3 */

__device__ int   g_fps[NC];
__device__ int   g_nbr[NC*KK];
__device__ int   g_cnt[NC];
__device__ float g_F1[(size_t)BB*NPP*HID];

__device__ __forceinline__ float d2f(float ax,float ay,float az,float bx,float by,float bz){
    float dx=__fsub_rn(ax,bx), dy=__fsub_rn(ay,by), dz=__fsub_rn(az,bz);
    return __fadd_rn(__fadd_rn(__fmul_rn(dx,dx),__fmul_rn(dy,dy)),__fmul_rn(dz,dz));
}

/* ---- packed fp32x2 helpers (sm_103a, per-lane IEEE-exact) ---- */
__device__ __forceinline__ void fma2(unsigned long long &d, unsigned long long a, unsigned long long b){
    asm("fma.rn.f32x2 %0, %1, %2, %0;" : "+l"(d) : "l"(a), "l"(b));
}
__device__ __forceinline__ unsigned long long add2(unsigned long long a, unsigned long long b){
    unsigned long long r; asm("add.rn.f32x2 %0, %1, %2;" : "=l"(r) : "l"(a), "l"(b)); return r;
}
__device__ __forceinline__ unsigned long long mul2(unsigned long long a, unsigned long long b){
    unsigned long long r; asm("mul.rn.f32x2 %0, %1, %2;" : "=l"(r) : "l"(a), "l"(b)); return r;
}
__device__ __forceinline__ unsigned long long splat2(float x){
    unsigned long long r; unsigned u = __float_as_uint(x);
    asm("mov.b64 %0, {%1, %1};" : "=l"(r) : "r"(u)); return r;
}
__device__ __forceinline__ void unpack2(unsigned long long v, float &lo, float &hi){
    unsigned a,b; asm("mov.b64 {%0, %1}, %2;" : "=r"(a), "=r"(b) : "l"(v));
    lo = __uint_as_float(a); hi = __uint_as_float(b);
}
__device__ __forceinline__ unsigned long long pack2(float lo, float hi){
    unsigned long long r;
    asm("mov.b64 %0, {%1, %2};" : "=l"(r) : "r"(__float_as_uint(lo)), "r"(__float_as_uint(hi)));
    return r;
}

// ---------------------------------------------------------------------------
// Kernel 1: fused FPS (blocks 0..15) + F1 (blocks 16..143).
// FPS: one barrier/iter, parity-double-buffered warp partials, every warp
// redundantly computes the final reduce. Packed f32x2 distance math.
// ---------------------------------------------------------------------------
__global__ void __launch_bounds__(1024,1) fpsf1_kernel(const float* __restrict__ point,
                                                       const float* __restrict__ xyz,
                                                       const float* __restrict__ W1,
                                                       const float* __restrict__ b1){
    extern __shared__ float sm[];
    int tid = threadIdx.x, lane = tid & 31, warp = tid >> 5;

    if (blockIdx.x < BB){
        float* px = sm;
        float* py = sm +   NPP;
        float* pz = sm + 2*NPP;
        __shared__ unsigned long long wpS[2][32];

        int b = blockIdx.x;
        const float* P = point + (size_t)b*NPP*3;
        float x[4], y[4], z[4], d[4];
        #pragma unroll
        for (int r = 0; r < 4; r++){
            int i = tid + r*1024;
            float a0 = P[i*3+0], a1 = P[i*3+1], a2 = P[i*3+2];
            px[i] = a0; py[i] = a1; pz[i] = a2;
            x[r] = a0; y[r] = a1; z[r] = a2;
            d[r] = 3.402823466e38f;
        }
        /* pack point pairs once: lanes {r, r+1} of the f32x2 */
        unsigned long long xp[2] = { pack2(x[0], x[1]), pack2(x[2], x[3]) };
        unsigned long long yp[2] = { pack2(y[0], y[1]), pack2(y[2], y[3]) };
        unsigned long long zp[2] = { pack2(z[0], z[1]), pack2(z[2], z[3]) };
        if (tid == 0) g_fps[b*MM] = 0;
        __syncthreads();

        int last = 0;
        int par  = 0;
        for (int m = 1; m < MM; m++){
            float cx = px[last], cy = py[last], cz = pz[last];
            unsigned long long ncx = splat2(-cx), ncy = splat2(-cy), ncz = splat2(-cz);

            float bv = -1.f; int bi = 0;
            #pragma unroll
            for (int g = 0; g < 2; g++){
                unsigned long long dx = add2(xp[g], ncx);
                unsigned long long dy = add2(yp[g], ncy);
                unsigned long long dz = add2(zp[g], ncz);
                unsigned long long ss = add2(add2(mul2(dx,dx), mul2(dy,dy)), mul2(dz,dz));
                float s0, s1; unpack2(ss, s0, s1);
                float v0 = fminf(d[2*g  ], s0); d[2*g  ] = v0;
                float v1 = fminf(d[2*g+1], s1); d[2*g+1] = v1;
                /* ascending global idx within thread -> strict '>' keeps first max */
                if (v0 > bv){ bv = v0; bi = tid + (2*g  )*1024; }
                if (v1 > bv){ bv = v1; bi = tid + (2*g+1)*1024; }
            }
            unsigned bits = __float_as_uint(bv);             /* v>=0: monotonic */
            unsigned wmax = __reduce_max_sync(0xffffffffu, bits);
            unsigned cand = (bits == wmax) ? (unsigned)bi : 0xffffffffu;
            unsigned widx = __reduce_min_sync(0xffffffffu, cand);
            if (lane == 0)
                wpS[par][warp] = (((unsigned long long)wmax) << 32) | widx;
            __syncthreads();
            /* every warp redundantly reduces the 32 partials */
            unsigned long long v = wpS[par][lane];
            unsigned hb = (unsigned)(v >> 32), lw = (unsigned)v;
            unsigned gmax = __reduce_max_sync(0xffffffffu, hb);
            unsigned c2   = (hb == gmax) ? lw : 0xffffffffu;
            unsigned gidx = __reduce_min_sync(0xffffffffu, c2);
            last = (int)gidx;
            if (tid == 0) g_fps[b*MM + m] = last;
            par ^= 1;
        }
    } else {
        /* F1: 2 threads per row, 32 outputs each */
        float* W1s = sm;          /* 4096 */
        float* b1s = sm + 4096;   /* 64   */
        for (int i = tid; i < CIN*HID; i += 1024) W1s[i] = W1[i];
        if (tid < HID) b1s[tid] = b1[tid];
        __syncthreads();

        int row  = (blockIdx.x - BB)*512 + (tid >> 1);
        int half = tid & 1;
        float acc[32];
        #pragma unroll
        for (int o = 0; o < 32; o++) acc[o] = b1s[half*32 + o];
        const float4* xr = (const float4*)(xyz + (size_t)row*CIN);
        #pragma unroll
        for (int q = 0; q < 16; q++){
            float4 xv = xr[q];
            float av[4] = {xv.x, xv.y, xv.z, xv.w};
            #pragma unroll
            for (int t = 0; t < 4; t++){
                float a = av[t];
                const float4* w = (const float4*)(W1s + (q*4+t)*HID + half*32);
                #pragma unroll
                for (int u = 0; u < 8; u++){
                    float4 wv4 = w[u];
                    acc[4*u]   = fmaf(a, wv4.x, acc[4*u]);
                    acc[4*u+1] = fmaf(a, wv4.y, acc[4*u+1]);
                    acc[4*u+2] = fmaf(a, wv4.z, acc[4*u+2]);
                    acc[4*u+3] = fmaf(a, wv4.w, acc[4*u+3]);
                }
            }
        }
        float4* o4 = (float4*)(g_F1 + (size_t)row*HID + half*32);
        #pragma unroll
        for (int u = 0; u < 8; u++)
            o4[u] = make_float4(acc[4*u], acc[4*u+1], acc[4*u+2], acc[4*u+3]);
    }
}

// ---------------------------------------------------------------------------
// Kernel 2: radius + exact top-K. One block serves 16 centers of one cloud.
// ---------------------------------------------------------------------------
__global__ void __launch_bounds__(256) nbr_kernel(const float* __restrict__ point){
    extern __shared__ float sm[];
    float* px = sm;
    float* py = sm +   NPP;
    float* pz = sm + 2*NPP;
    unsigned long long* keys = (unsigned long long*)(sm + 3*NPP);  /* 512 */
    __shared__ int ncand[16];

    int tid = threadIdx.x;
    int c0  = blockIdx.x*16;
    int b   = c0 >> 10;
    const float* P = point + (size_t)b*NPP*3;
    for (int i = tid; i < NPP; i += 256){
        px[i] = P[i*3+0]; py[i] = P[i*3+1]; pz[i] = P[i*3+2];
    }
    if (tid < 16) ncand[tid] = 0;
    __syncthreads();

    for (int ci = 0; ci < 16; ci++){
        int c  = c0 + ci;
        int cl = g_fps[c];
        float cx = px[cl], cy = py[cl], cz = pz[cl];
        for (int i = tid; i < NPP; i += 256){
            float d2 = d2f(px[i], py[i], pz[i], cx, cy, cz);
            if (d2 < R2){
                int p = atomicAdd(&ncand[ci], 1);
                if (p < 512)
                    keys[p] = (((unsigned long long)__float_as_uint(d2)) << 32) | (unsigned)i;
            }
        }
        __syncthreads();
        int n   = min(ncand[ci], 512);
        int cnt = min(n, KK);
        if (tid == 0) g_cnt[c] = cnt;
        for (int i = tid; i < n; i += 256){
            unsigned long long k = keys[i];
            int rank = 0;
            for (int j = 0; j < n; j++) rank += (keys[j] < k);
            if (rank < KK) g_nbr[c*KK + rank] = (int)(k & 0xffffffffu);
        }
        for (int i = cnt + tid; i < KK; i += 256) g_nbr[c*KK + i] = cl;
        __syncthreads();
    }
}

// ---------------------------------------------------------------------------
// Kernel 3: MLP, register-tiled FFMA2 GEMM. W3 from global (L1) -> 2 blocks/SM.
// ---------------------------------------------------------------------------
__global__ void __launch_bounds__(256,2) mlp_kernel(const float* __restrict__ point,
                                                    const float* __restrict__ W1,
                                                    const float* __restrict__ W2,
                                                    const float* __restrict__ b2,
                                                    const float* __restrict__ W3,
                                                    const float* __restrict__ b3,
                                                    float* __restrict__ out){
    extern __shared__ float sm[];
    float* buf  = sm;            /* 16384 : [64][256] activations (h1, then h2) */
    float* W2s  = sm + 16384;    /* 4096  */
    float* Wp   = sm + 20480;    /* 192   */
    float* b2s  = sm + 20672;    /* 64    */
    float* b3s  = sm + 20736;    /* 128   */

    int tid = threadIdx.x, lane = tid & 31, wid = tid >> 5;
    for (int i = tid; i < 4096; i += 256) W2s[i] = W2[i];
    if (tid < 192) Wp[tid]  = W1[4096 + tid];
    if (tid < 64)  b2s[tid] = b2[tid];
    if (tid < 128) b3s[tid] = b3[tid];

    int c0 = blockIdx.x*4;
    int b  = c0 >> 10;
    const float* P = point + (size_t)b*NPP*3;

    int ci   = tid >> 6;
    int cl   = g_fps[c0 + ci];
    int j    = g_nbr[blockIdx.x*256 + tid];
    __syncthreads();

    float dx = __fsub_rn(P[j*3+0], P[cl*3+0]);
    float dy = __fsub_rn(P[j*3+1], P[cl*3+1]);
    float dz = __fsub_rn(P[j*3+2], P[cl*3+2]);

    float h1[HID];
    const float4* fv = (const float4*)(g_F1 + (size_t)(b*NPP + j)*HID);
    #pragma unroll
    for (int q = 0; q < 16; q++){
        float4 v = fv[q];
        h1[4*q]=v.x; h1[4*q+1]=v.y; h1[4*q+2]=v.z; h1[4*q+3]=v.w;
    }
    #pragma unroll
    for (int i = 0; i < HID; i++){
        float v = h1[i];
        v = fmaf(dx, Wp[i],       v);
        v = fmaf(dy, Wp[64 + i],  v);
        v = fmaf(dz, Wp[128 + i], v);
        h1[i] = fmaxf(v, 0.f);
    }
    #pragma unroll
    for (int k = 0; k < HID; k++) buf[k*256 + tid] = h1[k];
    __syncthreads();

    int ow = wid*8;

    /* h2 = relu(h1 @ W2 + b2) */
    {
        unsigned long long acc[4][8];
        #pragma unroll
        for (int o = 0; o < 8; o++){
            unsigned long long bv = splat2(b2s[ow + o]);
            #pragma unroll
            for (int i = 0; i < 4; i++) acc[i][o] = bv;
        }
        const float* bptr = buf + 2*lane;
        #pragma unroll 4
        for (int k = 0; k < HID; k++){
            unsigned long long A2[4];
            #pragma unroll
            for (int i = 0; i < 4; i++)
                A2[i] = *(const unsigned long long*)(bptr + k*256 + 64*i);
            float4 w0 = *(const float4*)(W2s + k*64 + ow);
            float4 w1 = *(const float4*)(W2s + k*64 + ow + 4);
            unsigned long long B2[8] = { splat2(w0.x), splat2(w0.y), splat2(w0.z), splat2(w0.w),
                                         splat2(w1.x), splat2(w1.y), splat2(w1.z), splat2(w1.w) };
            #pragma unroll
            for (int o = 0; o < 8; o++)
                #pragma unroll
                for (int i = 0; i < 4; i++)
                    fma2(acc[i][o], A2[i], B2[o]);
        }
        __syncthreads();
        #pragma unroll
        for (int o = 0; o < 8; o++)
            #pragma unroll
            for (int i = 0; i < 4; i++){
                float lo, hi; unpack2(acc[i][o], lo, hi);
                *(unsigned long long*)(buf + (ow+o)*256 + 2*lane + 64*i) =
                    pack2(fmaxf(lo, 0.f), fmaxf(hi, 0.f));
            }
        __syncthreads();
    }

    int cnt4[4];
    #pragma unroll
    for (int i = 0; i < 4; i++) cnt4[i] = g_cnt[c0 + i];

    #pragma unroll
    for (int pass = 0; pass < 2; pass++){
        unsigned long long acc[4][8];
        #pragma unroll
        for (int o = 0; o < 8; o++){
            unsigned long long bv = splat2(b3s[pass*64 + ow + o]);
            #pragma unroll
            for (int i = 0; i < 4; i++) acc[i][o] = bv;
        }
        const float* bptr = buf + 2*lane;
        #pragma unroll 4
        for (int k = 0; k < HID; k++){
            unsigned long long A2[4];
            #pragma unroll
            for (int i = 0; i < 4; i++)
                A2[i] = *(const unsigned long long*)(bptr + k*256 + 64*i);
            const float* w = W3 + k*128 + pass*64 + ow;
            float4 w0 = *(const float4*)(w);
            float4 w1 = *(const float4*)(w + 4);
            unsigned long long B2[8] = { splat2(w0.x), splat2(w0.y), splat2(w0.z), splat2(w0.w),
                                         splat2(w1.x), splat2(w1.y), splat2(w1.z), splat2(w1.w) };
            #pragma unroll
            for (int o = 0; o < 8; o++)
                #pragma unroll
                for (int i = 0; i < 4; i++)
                    fma2(acc[i][o], A2[i], B2[o]);
        }
        #pragma unroll
        for (int i = 0; i < 4; i++){
            bool v0 = (2*lane)     < cnt4[i];
            bool v1 = (2*lane + 1) < cnt4[i];
            #pragma unroll
            for (int o = 0; o < 8; o++){
                float lo, hi; unpack2(acc[i][o], lo, hi);
                lo = v0 ? fmaxf(lo, 0.f) : -3.402823466e38f;
                hi = v1 ? fmaxf(hi, 0.f) : -3.402823466e38f;
                float m = fmaxf(lo, hi);
                #pragma unroll
                for (int s = 16; s; s >>= 1)
                    m = fmaxf(m, __shfl_xor_sync(0xffffffffu, m, s));
                if (lane == 0)
                    out[(size_t)(c0 + i)*OUTD + pass*64 + ow + o] = m;
            }
        }
    }
}

// ---------------------------------------------------------------------------
// Kernel 4: centers + batch output segments.
// ---------------------------------------------------------------------------
__global__ void aux_kernel(const float* __restrict__ point, float* __restrict__ out){
    int t = blockIdx.x*blockDim.x + threadIdx.x;
    if (t < NC){
        int b  = t >> 10;
        int gi = b*NPP + g_fps[t];
        out[OFF_C + t*3 + 0] = point[gi*3 + 0];
        out[OFF_C + t*3 + 1] = point[gi*3 + 1];
        out[OFF_C + t*3 + 2] = point[gi*3 + 2];
        out[OFF_B + t] = (float)b;
    }
}

extern "C" void kernel_launch(void* const* d_in, const int* in_sizes, int n_in,
                              void* d_out, int out_size){
    const float *xyz=nullptr, *point=nullptr, *W1=nullptr, *b1=nullptr,
                *W2=nullptr, *b2=nullptr, *W3=nullptr, *b3=nullptr;
    int n64 = 0;
    for (int i = 0; i < n_in; i++){
        switch (in_sizes[i]){
            case 4194304: xyz   = (const float*)d_in[i]; break;
            case 196608:  point = (const float*)d_in[i]; break;
            case 4288:    W1    = (const float*)d_in[i]; break;
            case 4096:    W2    = (const float*)d_in[i]; break;
            case 8192:    W3    = (const float*)d_in[i]; break;
            case 64:      if (n64++ == 0) b1 = (const float*)d_in[i];
                          else            b2 = (const float*)d_in[i]; break;
            case 128:     b3    = (const float*)d_in[i]; break;
            default: break;
        }
    }
    float* out = (float*)d_out;

    int fps_smem = 3*NPP*(int)sizeof(float);
    int nbr_smem = 3*NPP*(int)sizeof(float) + 512*8 + 16;
    int mlp_smem = 20864*(int)sizeof(float);
    cudaFuncSetAttribute(fpsf1_kernel, cudaFuncAttributeMaxDynamicSharedMemorySize, fps_smem);
    cudaFuncSetAttribute(nbr_kernel,   cudaFuncAttributeMaxDynamicSharedMemorySize, nbr_smem);
    cudaFuncSetAttribute(mlp_kernel,   cudaFuncAttributeMaxDynamicSharedMemorySize, mlp_smem);

    fpsf1_kernel<<<BB + BB*NPP/512, 1024, fps_smem>>>(point, xyz, W1, b1);
    nbr_kernel<<<NC/16, 256, nbr_smem>>>(point);
    mlp_kernel<<<NC/4, 256, mlp_smem>>>(point, W1, W2, b2, W3, b3, out);
    aux_kernel<<<(NC+255)/256, 256>>>(point, out);
}

// round 5
// speedup vs baseline: 2.3699x; 1.1414x over previous
#include <cuda_runtime.h>
#include <cstdint>

#define BB   16
#define NPP  4096
#define CIN  64
#define MM   1024
#define KK   64
#define HID  64
#define OUTD 128
#define NC   (BB*MM)
#define R2   0.04f

#define OFF_C 2097152         /* NC*OUTD */
#define OFF_B 2146304         /* OFF_C + NC*3 */

#define NF1    128            /* f1 tasks: 512 rows each            */
#define NTNBR  1024           /* nbr tasks: 16 centers each         */
#define NTMLP  2048           /* mlp tasks: 8 centers each          */
#define GRID   148
#define NTHR   512

typedef unsigned long long ull;

__device__ int   g_fps[NC];
__device__ int   g_nbr[NC*KK];
__device__ int   g_cnt[NC];
__device__ float g_F1[(size_t)BB*NPP*HID];
__device__ int   g_cf1, g_cnbr, g_cmlp, g_f1done;
__device__ int   g_prog[BB];
__device__ int   g_flag[NTNBR];

__device__ __forceinline__ float d2f(float ax,float ay,float az,float bx,float by,float bz){
    float dx=__fsub_rn(ax,bx), dy=__fsub_rn(ay,by), dz=__fsub_rn(az,bz);
    return __fadd_rn(__fadd_rn(__fmul_rn(dx,dx),__fmul_rn(dy,dy)),__fmul_rn(dz,dz));
}

/* ---- packed fp32x2 helpers (sm_103a, per-lane IEEE-exact) ---- */
__device__ __forceinline__ void fma2(ull &d, ull a, ull b){
    asm("fma.rn.f32x2 %0, %1, %2, %0;" : "+l"(d) : "l"(a), "l"(b));
}
__device__ __forceinline__ ull add2(ull a, ull b){
    ull r; asm("add.rn.f32x2 %0, %1, %2;" : "=l"(r) : "l"(a), "l"(b)); return r;
}
__device__ __forceinline__ ull mul2(ull a, ull b){
    ull r; asm("mul.rn.f32x2 %0, %1, %2;" : "=l"(r) : "l"(a), "l"(b)); return r;
}
__device__ __forceinline__ ull splat2(float x){
    ull r; unsigned u = __float_as_uint(x);
    asm("mov.b64 %0, {%1, %1};" : "=l"(r) : "r"(u)); return r;
}
__device__ __forceinline__ void unpack2(ull v, float &lo, float &hi){
    unsigned a,b; asm("mov.b64 {%0, %1}, %2;" : "=r"(a), "=r"(b) : "l"(v));
    lo = __uint_as_float(a); hi = __uint_as_float(b);
}
__device__ __forceinline__ ull pack2(float lo, float hi){
    ull r;
    asm("mov.b64 %0, {%1, %2};" : "=l"(r) : "r"(__float_as_uint(lo)), "r"(__float_as_uint(hi)));
    return r;
}
__device__ __forceinline__ int vload(const int* p){ return *(volatile const int*)p; }

// ---------------------------------------------------------------------------
// FPS producer: one block per cloud, 512 threads, 8 pts/thread in registers.
// Publishes g_prog[b] (release) every 64 centers.
// ---------------------------------------------------------------------------
__device__ void do_fps(float* sm, int tid, int b, const float* __restrict__ point){
    float* px = sm; float* py = sm + NPP; float* pz = sm + 2*NPP;
    __shared__ ull wpS[2][32];
    int lane = tid & 31, warp = tid >> 5;

    const float* P = point + (size_t)b*NPP*3;
    float x[8], y[8], z[8], d[8];
    #pragma unroll
    for (int r = 0; r < 8; r++){
        int i = tid + r*NTHR;
        float a0 = P[i*3+0], a1 = P[i*3+1], a2 = P[i*3+2];
        px[i] = a0; py[i] = a1; pz[i] = a2;
        x[r] = a0; y[r] = a1; z[r] = a2;
        d[r] = 3.402823466e38f;
    }
    ull xp[4], yp[4], zp[4];
    #pragma unroll
    for (int g = 0; g < 4; g++){
        xp[g] = pack2(x[2*g], x[2*g+1]);
        yp[g] = pack2(y[2*g], y[2*g+1]);
        zp[g] = pack2(z[2*g], z[2*g+1]);
    }
    if (tid < 64) ((ull*)wpS)[tid] = 0ull;
    if (tid == 0) g_fps[b*MM] = 0;
    __syncthreads();

    int last = 0, par = 0;
    for (int m = 1; m < MM; m++){
        float cx = px[last], cy = py[last], cz = pz[last];
        ull ncx = splat2(-cx), ncy = splat2(-cy), ncz = splat2(-cz);

        float bv = -1.f; int bi = 0;
        #pragma unroll
        for (int g = 0; g < 4; g++){
            ull dx = add2(xp[g], ncx);
            ull dy = add2(yp[g], ncy);
            ull dz = add2(zp[g], ncz);
            ull ss = add2(add2(mul2(dx,dx), mul2(dy,dy)), mul2(dz,dz));
            float s0, s1; unpack2(ss, s0, s1);
            float v0 = fminf(d[2*g  ], s0); d[2*g  ] = v0;
            float v1 = fminf(d[2*g+1], s1); d[2*g+1] = v1;
            if (v0 > bv){ bv = v0; bi = tid + (2*g  )*NTHR; }
            if (v1 > bv){ bv = v1; bi = tid + (2*g+1)*NTHR; }
        }
        unsigned bits = __float_as_uint(bv);
        unsigned wmax = __reduce_max_sync(0xffffffffu, bits);
        unsigned cand = (bits == wmax) ? (unsigned)bi : 0xffffffffu;
        unsigned widx = __reduce_min_sync(0xffffffffu, cand);
        if (lane == 0) wpS[par][warp] = (((ull)wmax) << 32) | widx;
        __syncthreads();
        ull v = wpS[par][lane];
        unsigned hb = (unsigned)(v >> 32), lw = (unsigned)v;
        unsigned gmax = __reduce_max_sync(0xffffffffu, hb);
        unsigned c2   = (hb == gmax) ? lw : 0xffffffffu;
        unsigned gidx = __reduce_min_sync(0xffffffffu, c2);
        last = (int)gidx;
        if (tid == 0){
            g_fps[b*MM + m] = last;
            if ((m & 63) == 63){ __threadfence(); atomicExch(&g_prog[b], m + 1); }
        }
        par ^= 1;
    }
}

// ---------------------------------------------------------------------------
// F1 task: 512 rows, F1[row] = xyz[row] @ W1[:64] + b1.
// ---------------------------------------------------------------------------
__device__ void do_f1(float* sm, int tid, int id,
                      const float* __restrict__ xyz,
                      const float* __restrict__ W1,
                      const float* __restrict__ b1){
    float* W1s = sm;                 /* 4096 + 64 */
    for (int i = tid; i < CIN*HID; i += NTHR) W1s[i] = W1[i];
    if (tid < HID) W1s[4096 + tid] = b1[tid];
    __syncthreads();

    int row = id*NTHR + tid;
    float acc[HID];
    #pragma unroll
    for (int o = 0; o < HID; o++) acc[o] = W1s[4096 + o];
    const float4* xr = (const float4*)(xyz + (size_t)row*CIN);
    #pragma unroll
    for (int q = 0; q < 16; q++){
        float4 xv = xr[q];
        float av[4] = {xv.x, xv.y, xv.z, xv.w};
        #pragma unroll
        for (int t = 0; t < 4; t++){
            float a = av[t];
            const float4* w = (const float4*)(W1s + (q*4+t)*HID);
            #pragma unroll
            for (int u = 0; u < 16; u++){
                float4 wv4 = w[u];
                acc[4*u]   = fmaf(a, wv4.x, acc[4*u]);
                acc[4*u+1] = fmaf(a, wv4.y, acc[4*u+1]);
                acc[4*u+2] = fmaf(a, wv4.z, acc[4*u+2]);
                acc[4*u+3] = fmaf(a, wv4.w, acc[4*u+3]);
            }
        }
    }
    float4* o4 = (float4*)(g_F1 + (size_t)row*HID);
    #pragma unroll
    for (int u = 0; u < 16; u++)
        o4[u] = make_float4(acc[4*u], acc[4*u+1], acc[4*u+2], acc[4*u+3]);

    __threadfence();
    __syncthreads();
    if (tid == 0) atomicAdd(&g_f1done, 1);
}

// ---------------------------------------------------------------------------
// nbr task: 16 centers of one cloud (gated on g_prog), + centers/batch output.
// ---------------------------------------------------------------------------
__device__ void do_nbr(float* sm, int tid, int id,
                       const float* __restrict__ point, float* __restrict__ out){
    float* px = sm; float* py = sm + NPP; float* pz = sm + 2*NPP;
    ull* keys = (ull*)(sm + 3*NPP);     /* 512 */
    __shared__ int ncand[16];

    int cloud = id & 15, chunk = id >> 4;
    int c0g = cloud*MM + chunk*16;
    if (tid == 0){
        while (vload(&g_prog[cloud]) < chunk*16 + 16) __nanosleep(200);
    }
    __syncthreads();
    __threadfence();   /* acquire: flush L1 before reading g_fps */

    const float* P = point + (size_t)cloud*NPP*3;
    for (int i = tid; i < NPP; i += NTHR){
        px[i] = P[i*3+0]; py[i] = P[i*3+1]; pz[i] = P[i*3+2];
    }
    if (tid < 16) ncand[tid] = 0;
    __syncthreads();

    for (int ci = 0; ci < 16; ci++){
        int c  = c0g + ci;
        int cl = g_fps[c];
        float cx = px[cl], cy = py[cl], cz = pz[cl];
        for (int i = tid; i < NPP; i += NTHR){
            float d2 = d2f(px[i], py[i], pz[i], cx, cy, cz);
            if (d2 < R2){
                int p = atomicAdd(&ncand[ci], 1);
                if (p < 512)
                    keys[p] = (((ull)__float_as_uint(d2)) << 32) | (unsigned)i;
            }
        }
        __syncthreads();
        int n   = min(ncand[ci], 512);
        int cnt = min(n, KK);
        if (tid == 0) g_cnt[c] = cnt;
        for (int i = tid; i < n; i += NTHR){
            ull k = keys[i];
            int rank = 0;
            for (int jj = 0; jj < n; jj++) rank += (keys[jj] < k);
            if (rank < KK) g_nbr[c*KK + rank] = (int)(k & 0xffffffffu);
        }
        for (int i = cnt + tid; i < KK; i += NTHR) g_nbr[c*KK + i] = cl;
        __syncthreads();
    }
    if (tid < 16){
        int c = c0g + tid; int cl = g_fps[c];
        out[OFF_C + c*3 + 0] = px[cl];
        out[OFF_C + c*3 + 1] = py[cl];
        out[OFF_C + c*3 + 2] = pz[cl];
        out[OFF_B + c] = (float)cloud;
    }
    __threadfence();
    __syncthreads();
    if (tid == 0) atomicExch(&g_flag[id], 1);
}

// ---------------------------------------------------------------------------
// mlp task: 8 centers = two 256-thread sub-tiles, gated on nbr flag + f1done.
// ---------------------------------------------------------------------------
__device__ void do_mlp(float* sm, int tid, int id,
                       const float* __restrict__ point,
                       const float* __restrict__ W1, const float* __restrict__ W2,
                       const float* __restrict__ b2, const float* __restrict__ W3,
                       const float* __restrict__ b3, float* __restrict__ out){
    float* buf = sm;                 /* 2 x 16384 */
    float* W2s = sm + 32768;         /* 4096 */
    float* Wp  = sm + 36864;         /* 192  */
    float* b2s = sm + 37056;         /* 64   */
    float* b3s = sm + 37120;         /* 128  */

    if (tid == 0){
        int fl = ((id >> 5) << 4) | (id & 15);
        while (!(vload(&g_flag[fl]) && vload(&g_f1done) >= NF1)) __nanosleep(200);
    }
    __syncthreads();
    __threadfence();   /* acquire */

    int lane = tid & 31;
    int sub  = tid >> 8;
    int stid = tid & 255;
    float* bufX = buf + sub*16384;

    for (int i = tid; i < 4096; i += NTHR) W2s[i] = W2[i];
    if (tid < 192) Wp[tid]  = W1[4096 + tid];
    if (tid < 64)  b2s[tid] = b2[tid];
    if (tid < 128) b3s[tid] = b3[tid];

    int cloud = id & 15;
    int c0s = cloud*MM + (id >> 4)*8 + sub*4;
    const float* P = point + (size_t)cloud*NPP*3;

    int ci = stid >> 6;
    int cl = g_fps[c0s + ci];
    int j  = g_nbr[c0s*KK + stid];
    __syncthreads();   /* weights ready */

    float dx = __fsub_rn(P[j*3+0], P[cl*3+0]);
    float dy = __fsub_rn(P[j*3+1], P[cl*3+1]);
    float dz = __fsub_rn(P[j*3+2], P[cl*3+2]);

    float h1[HID];
    const float4* fv = (const float4*)(g_F1 + (size_t)(cloud*NPP + j)*HID);
    #pragma unroll
    for (int q = 0; q < 16; q++){
        float4 v = fv[q];
        h1[4*q]=v.x; h1[4*q+1]=v.y; h1[4*q+2]=v.z; h1[4*q+3]=v.w;
    }
    #pragma unroll
    for (int i = 0; i < HID; i++){
        float v = h1[i];
        v = fmaf(dx, Wp[i],       v);
        v = fmaf(dy, Wp[64 + i],  v);
        v = fmaf(dz, Wp[128 + i], v);
        h1[i] = fmaxf(v, 0.f);
    }
    #pragma unroll
    for (int k = 0; k < HID; k++) bufX[k*256 + stid] = h1[k];
    __syncthreads();

    int ow = (stid >> 5)*8;

    /* h2 = relu(h1 @ W2 + b2) */
    {
        ull acc[4][8];
        #pragma unroll
        for (int o = 0; o < 8; o++){
            ull bv = splat2(b2s[ow + o]);
            #pragma unroll
            for (int i = 0; i < 4; i++) acc[i][o] = bv;
        }
        const float* bptr = bufX + 2*lane;
        #pragma unroll 4
        for (int k = 0; k < HID; k++){
            ull A2[4];
            #pragma unroll
            for (int i = 0; i < 4; i++)
                A2[i] = *(const ull*)(bptr + k*256 + 64*i);
            float4 w0 = *(const float4*)(W2s + k*64 + ow);
            float4 w1 = *(const float4*)(W2s + k*64 + ow + 4);
            ull B2[8] = { splat2(w0.x), splat2(w0.y), splat2(w0.z), splat2(w0.w),
                          splat2(w1.x), splat2(w1.y), splat2(w1.z), splat2(w1.w) };
            #pragma unroll
            for (int o = 0; o < 8; o++)
                #pragma unroll
                for (int i = 0; i < 4; i++)
                    fma2(acc[i][o], A2[i], B2[o]);
        }
        __syncthreads();
        #pragma unroll
        for (int o = 0; o < 8; o++)
            #pragma unroll
            for (int i = 0; i < 4; i++){
                float lo, hi; unpack2(acc[i][o], lo, hi);
                *(ull*)(bufX + (ow+o)*256 + 2*lane + 64*i) =
                    pack2(fmaxf(lo, 0.f), fmaxf(hi, 0.f));
            }
        __syncthreads();
    }

    int cnt4[4];
    #pragma unroll
    for (int i = 0; i < 4; i++) cnt4[i] = g_cnt[c0s + i];

    #pragma unroll
    for (int pass = 0; pass < 2; pass++){
        ull acc[4][8];
        #pragma unroll
        for (int o = 0; o < 8; o++){
            ull bv = splat2(b3s[pass*64 + ow + o]);
            #pragma unroll
            for (int i = 0; i < 4; i++) acc[i][o] = bv;
        }
        const float* bptr = bufX + 2*lane;
        #pragma unroll 4
        for (int k = 0; k < HID; k++){
            ull A2[4];
            #pragma unroll
            for (int i = 0; i < 4; i++)
                A2[i] = *(const ull*)(bptr + k*256 + 64*i);
            const float* w = W3 + k*128 + pass*64 + ow;
            float4 w0 = *(const float4*)(w);
            float4 w1 = *(const float4*)(w + 4);
            ull B2[8] = { splat2(w0.x), splat2(w0.y), splat2(w0.z), splat2(w0.w),
                          splat2(w1.x), splat2(w1.y), splat2(w1.z), splat2(w1.w) };
            #pragma unroll
            for (int o = 0; o < 8; o++)
                #pragma unroll
                for (int i = 0; i < 4; i++)
                    fma2(acc[i][o], A2[i], B2[o]);
        }
        #pragma unroll
        for (int i = 0; i < 4; i++){
            bool v0 = (2*lane)     < cnt4[i];
            bool v1 = (2*lane + 1) < cnt4[i];
            #pragma unroll
            for (int o = 0; o < 8; o++){
                float lo, hi; unpack2(acc[i][o], lo, hi);
                lo = v0 ? fmaxf(lo, 0.f) : -3.402823466e38f;
                hi = v1 ? fmaxf(hi, 0.f) : -3.402823466e38f;
                float m = fmaxf(lo, hi);
                #pragma unroll
                for (int s = 16; s; s >>= 1)
                    m = fmaxf(m, __shfl_xor_sync(0xffffffffu, m, s));
                if (lane == 0)
                    out[(size_t)(c0s + i)*OUTD + pass*64 + ow + o] = m;
            }
        }
    }
}

// ---------------------------------------------------------------------------
// Init: reset queues/flags (separate launch, ordered before mega on stream).
// ---------------------------------------------------------------------------
__global__ void init_kernel(){
    int t = blockIdx.x*blockDim.x + threadIdx.x;
    if (t == 0){ g_cf1 = 0; g_cnbr = 0; g_cmlp = 0; g_f1done = 0; }
    if (t < BB) g_prog[t] = 0;
    if (t < NTNBR) g_flag[t] = 0;
}

// ---------------------------------------------------------------------------
// Mega kernel: blocks 0..15 FPS then join worker pool; others worker pool.
// ---------------------------------------------------------------------------
__global__ void __launch_bounds__(NTHR,1) mega_kernel(
        const float* __restrict__ point, const float* __restrict__ xyz,
        const float* __restrict__ W1, const float* __restrict__ b1,
        const float* __restrict__ W2, const float* __restrict__ b2,
        const float* __restrict__ W3, const float* __restrict__ b3,
        float* __restrict__ out){
    extern __shared__ float sm[];
    int tid = threadIdx.x;
    __shared__ int s_ph, s_id;

    if (blockIdx.x < BB) do_fps(sm, tid, blockIdx.x, point);
    __syncthreads();

    for (;;){
        if (tid == 0){
            int ph = -1, id = -1;
            if (vload(&g_cf1) < NF1){
                int t = atomicAdd(&g_cf1, 1);
                if (t < NF1){ ph = 0; id = t; }
            }
            if (ph < 0){
                int t = vload(&g_cnbr);
                if (t < NTNBR){
                    int cloud = t & 15, chunk = t >> 4;
                    if (vload(&g_prog[cloud]) >= chunk*16 + 16){
                        t = atomicAdd(&g_cnbr, 1);
                        if (t < NTNBR){ ph = 1; id = t; }
                    }
                }
            }
            if (ph < 0){
                int t = vload(&g_cmlp);
                if (t < NTMLP && vload(&g_f1done) >= NF1){
                    int fl = ((t >> 5) << 4) | (t & 15);
                    if (vload(&g_flag[fl])){
                        t = atomicAdd(&g_cmlp, 1);
                        if (t < NTMLP){ ph = 2; id = t; }
                    }
                }
            }
            if (ph < 0){
                if (vload(&g_cf1) >= NF1 && vload(&g_cnbr) >= NTNBR && vload(&g_cmlp) >= NTMLP)
                    ph = 3;
                else { __nanosleep(256); ph = 4; }
            }
            s_ph = ph; s_id = id;
        }
        __syncthreads();
        int ph = s_ph, id = s_id;
        if (ph == 3) break;
        if      (ph == 0) do_f1 (sm, tid, id, xyz, W1, b1);
        else if (ph == 1) do_nbr(sm, tid, id, point, out);
        else if (ph == 2) do_mlp(sm, tid, id, point, W1, W2, b2, W3, b3, out);
        __syncthreads();
    }
}

extern "C" void kernel_launch(void* const* d_in, const int* in_sizes, int n_in,
                              void* d_out, int out_size){
    const float *xyz=nullptr, *point=nullptr, *W1=nullptr, *b1=nullptr,
                *W2=nullptr, *b2=nullptr, *W3=nullptr, *b3=nullptr;
    int n64 = 0;
    for (int i = 0; i < n_in; i++){
        switch (in_sizes[i]){
            case 4194304: xyz   = (const float*)d_in[i]; break;
            case 196608:  point = (const float*)d_in[i]; break;
            case 4288:    W1    = (const float*)d_in[i]; break;
            case 4096:    W2    = (const float*)d_in[i]; break;
            case 8192:    W3    = (const float*)d_in[i]; break;
            case 64:      if (n64++ == 0) b1 = (const float*)d_in[i];
                          else            b2 = (const float*)d_in[i]; break;
            case 128:     b3    = (const float*)d_in[i]; break;
            default: break;
        }
    }
    float* out = (float*)d_out;

    int smem = 37248*(int)sizeof(float);   /* 148,992 B */
    cudaFuncSetAttribute(mega_kernel, cudaFuncAttributeMaxDynamicSharedMemorySize, smem);

    init_kernel<<<4, 256>>>();
    mega_kernel<<<GRID, NTHR, smem>>>(point, xyz, W1, b1, W2, b2, W3, b3, out);
}